// round 10
// baseline (speedup 1.0000x reference)
#include <cuda_runtime.h>
#include <cuda_bf16.h>

// Triplet margin loss, D=4096 fp32, B=24576 rows -> 8192 triplets.
// Pure HBM-streaming problem: read 402.7 MB once, emit one scalar.
//
// Warp-independent streaming. One triplet per WARP (8 per CTA), no smem
// and no __syncthreads in the hot path -> no CTA-wide load-issue bubbles at
// triplet boundaries. grid = triplets/8 = 1024 CTAs; launch_bounds(256,7)
// keeps regs<=36 so 7 CTAs/SM cover the grid in a single wave.

#define MARGIN 1.0f
#define D_DIM  4096
#define D4     (D_DIM / 4)      // 1024 float4 per row
#define NTHREADS 256
#define WARPS_PER_CTA (NTHREADS / 32)

__device__ float        g_loss_sum  = 0.0f;
__device__ unsigned int g_done_ctas = 0u;

__global__ __launch_bounds__(NTHREADS, 7) void tl_warp_kernel(
    const float4* __restrict__ x, float* __restrict__ out,
    int triplets, float inv_triplets)
{
    const int lane = threadIdx.x & 31;
    const int wid  = threadIdx.x >> 5;
    const int t    = blockIdx.x * WARPS_PER_CTA + wid;   // triplet for this warp

    float hinge = 0.0f;

    if (t < triplets) {
        const float4* __restrict__ q = x + (size_t)t * 3 * D4;
        const float4* __restrict__ p = q + D4;
        const float4* __restrict__ n = p + D4;

        float sqp = 0.0f;   // sum (q-p)^2
        float sqn = 0.0f;   // sum (q-n)^2

        // 1024 float4 per row / 32 lanes = 32 iterations. Each warp-load is
        // 512B contiguous (perfect coalescing). Unroll x2 -> 6 independent
        // LDG.128 per batch under the 36-reg budget (MLP hides DRAM latency).
        #pragma unroll 2
        for (int i = 0; i < D4 / 32; ++i) {
            const int idx = i * 32 + lane;
            const float4 qa = q[idx];
            const float4 pa = p[idx];
            const float4 na = n[idx];
            float d;
            d = qa.x - pa.x; sqp = fmaf(d, d, sqp);
            d = qa.y - pa.y; sqp = fmaf(d, d, sqp);
            d = qa.z - pa.z; sqp = fmaf(d, d, sqp);
            d = qa.w - pa.w; sqp = fmaf(d, d, sqp);
            d = qa.x - na.x; sqn = fmaf(d, d, sqn);
            d = qa.y - na.y; sqn = fmaf(d, d, sqn);
            d = qa.z - na.z; sqn = fmaf(d, d, sqn);
            d = qa.w - na.w; sqn = fmaf(d, d, sqn);
        }

        // Warp-only reduction of the pair (no smem, no barriers)
        #pragma unroll
        for (int off = 16; off > 0; off >>= 1) {
            sqp += __shfl_down_sync(0xFFFFFFFFu, sqp, off);
            sqn += __shfl_down_sync(0xFFFFFFFFu, sqn, off);
        }

        if (lane == 0) {
            const float h = MARGIN + sqrtf(sqp) - sqrtf(sqn);
            if (h > 0.0f) hinge = h;
        }
    }

    if (lane == 0 && hinge != 0.0f) atomicAdd(&g_loss_sum, hinge);

    // One barrier per CTA, only at the very end, for the finalize handshake.
    __syncthreads();

    if (threadIdx.x == 0) {
        __threadfence();
        const unsigned int old = atomicAdd(&g_done_ctas, 1u);
        if (old == gridDim.x - 1u) {
            // Last CTA: all adds visible (fence-before-arrive on every CTA).
            const float s = atomicAdd(&g_loss_sum, 0.0f);
            out[0] = fmaxf(s * inv_triplets, 0.0f);
            // Reset state for the next graph replay (atomics -> L2-resident).
            atomicExch(&g_loss_sum, 0.0f);
            __threadfence();
            atomicExch(&g_done_ctas, 0u);
        }
    }
}

extern "C" void kernel_launch(void* const* d_in, const int* in_sizes, int n_in,
                              void* d_out, int out_size) {
    const float4* x = (const float4*)d_in[0];
    float* out = (float*)d_out;

    const long long total = in_sizes[0];         // B * D
    const int triplets = (int)(total / (3LL * D_DIM));
    const int grid = (triplets + WARPS_PER_CTA - 1) / WARPS_PER_CTA;

    tl_warp_kernel<<<grid, NTHREADS>>>(x, out, triplets, 1.0f / (float)triplets);
}